// round 2
// baseline (speedup 1.0000x reference)
#include <cuda_runtime.h>
#include <cstdint>
#include <math.h>

#define B_ 64
#define S_ 2048
#define H_ 1024
#define M_ (B_*S_)   // 131072 rows of the big GEMM
#define NTILES 8     // H_/128 N-tiles

// Scratch (no allocations allowed): dec_proj and per-N-tile score partials.
__device__ float g_dp[B_ * H_];
__device__ float g_part[NTILES * M_];
__device__ int   g_mask_mode;   // 0=uint8, 1=int32, 2=float32

__device__ __forceinline__ uint32_t f2tf(float x) {
    uint32_t r;
    asm("cvt.rna.tf32.f32 %0, %1;" : "=r"(r) : "f"(x));
    return r;
}

__device__ __forceinline__ void mma_tf32(float c[4], const uint32_t a[4], const uint32_t b[2]) {
    asm volatile(
        "mma.sync.aligned.m16n8k8.row.col.f32.tf32.tf32.f32 "
        "{%0,%1,%2,%3}, {%4,%5,%6,%7}, {%8,%9}, {%0,%1,%2,%3};"
        : "+f"(c[0]), "+f"(c[1]), "+f"(c[2]), "+f"(c[3])
        : "r"(a[0]), "r"(a[1]), "r"(a[2]), "r"(a[3]), "r"(b[0]), "r"(b[1]));
}

// ---------------------------------------------------------------------------
// Kernel 0: sniff the mask dtype from its first word. Deterministic.
// uint8 all-true -> 0x01010101; float32 1.0f -> 0x3F800000; int32 1 -> 1.
// ---------------------------------------------------------------------------
__global__ void sniff_mask_kernel(const unsigned int* __restrict__ m) {
    unsigned w = m[0];
    int mode;
    if (w == 0x01010101u)      mode = 0;  // uint8/bool bytes
    else if (w == 0x3F800000u) mode = 2;  // float32
    else                       mode = 1;  // int32 (covers 0x00000001)
    g_mask_mode = mode;
}

// ---------------------------------------------------------------------------
// Kernel 1: dec_proj[b][o] = sum_h dec[b,h] * W_dec[o,h]
// One warp computes one o for 4 consecutive b (reuses W row 4x).
// ---------------------------------------------------------------------------
__global__ void dec_proj_kernel(const float* __restrict__ dec,
                                const float* __restrict__ Wdec) {
    int wid  = (blockIdx.x * blockDim.x + threadIdx.x) >> 5;
    int lane = threadIdx.x & 31;
    int o  = wid >> 4;          // 0..1023
    int b0 = (wid & 15) * 4;    // 0..60
    const float* wr = Wdec + (size_t)o * H_;
    const float* d0 = dec + (size_t)(b0 + 0) * H_;
    const float* d1 = dec + (size_t)(b0 + 1) * H_;
    const float* d2 = dec + (size_t)(b0 + 2) * H_;
    const float* d3 = dec + (size_t)(b0 + 3) * H_;
    float a0 = 0.f, a1 = 0.f, a2 = 0.f, a3 = 0.f;
    #pragma unroll 4
    for (int h = lane; h < H_; h += 32) {
        float w = wr[h];
        a0 = fmaf(w, d0[h], a0);
        a1 = fmaf(w, d1[h], a1);
        a2 = fmaf(w, d2[h], a2);
        a3 = fmaf(w, d3[h], a3);
    }
    #pragma unroll
    for (int off = 16; off; off >>= 1) {
        a0 += __shfl_down_sync(0xffffffffu, a0, off);
        a1 += __shfl_down_sync(0xffffffffu, a1, off);
        a2 += __shfl_down_sync(0xffffffffu, a2, off);
        a3 += __shfl_down_sync(0xffffffffu, a3, off);
    }
    if (lane == 0) {
        g_dp[(size_t)(b0 + 0) * H_ + o] = a0;
        g_dp[(size_t)(b0 + 1) * H_ + o] = a1;
        g_dp[(size_t)(b0 + 2) * H_ + o] = a2;
        g_dp[(size_t)(b0 + 3) * H_ + o] = a3;
    }
}

// ---------------------------------------------------------------------------
// Kernel 2: fused TF32 GEMM (enc @ W_enc^T) + tanh(.+dec_proj) . v reduction.
// Block tile 128x128x32; 8 warps (2 in M x 4 in N), warp tile 64x32.
// Writes g_part[ntile][m] = sum over this block's 128 cols of v*tanh(...).
// Grid: (8 N-tiles fastest, 1024 M-tiles) for L2 reuse of the A tile.
// ---------------------------------------------------------------------------
__global__ void __launch_bounds__(256, 1)
fused_score_kernel(const float* __restrict__ enc,
                   const float* __restrict__ Wenc,
                   const float* __restrict__ v) {
    __shared__ uint32_t As[128][36];   // [m][k], pad 36 -> conflict-free frags
    __shared__ uint32_t Bs[128][36];   // [n][k]
    __shared__ float dp_sh[128];
    __shared__ float v_sh[128];
    __shared__ float part_sh[4][128];

    const int tid   = threadIdx.x;
    const int lane  = tid & 31;
    const int warp  = tid >> 5;
    const int warpM = warp & 1;    // 0..1
    const int warpN = warp >> 1;   // 0..3
    const int g = lane >> 2;       // groupID
    const int t = lane & 3;        // threadID_in_group

    const int nBase = blockIdx.x * 128;
    const int mBase = blockIdx.y * 128;
    const int b     = mBase >> 11;        // / S_ (128 | 2048 so single b)

    if (tid < 128) {
        dp_sh[tid] = g_dp[(size_t)b * H_ + nBase + tid];
        v_sh[tid]  = v[nBase + tid];
    }

    float acc[4][4][4];
    #pragma unroll
    for (int mi = 0; mi < 4; mi++)
        #pragma unroll
        for (int ni = 0; ni < 4; ni++)
            #pragma unroll
            for (int c = 0; c < 4; c++) acc[mi][ni][c] = 0.f;

    // global staging: each thread owns 4 float4 of A and of B per k-tile
    const int rowB = tid >> 3;   // 0..31 base row; +i*32
    const int kq   = tid & 7;    // float4 slot within 32-wide k
    const float* Aptr = enc  + (size_t)(mBase + rowB) * H_ + kq * 4;
    const float* Bptr = Wenc + (size_t)(nBase + rowB) * H_ + kq * 4;

    float4 ar[4], br[4];

#define LOADT(KT) {                                                        \
    const size_t ko = (size_t)(KT) * 32;                                   \
    _Pragma("unroll")                                                      \
    for (int i = 0; i < 4; i++) {                                          \
        ar[i] = *(const float4*)(Aptr + (size_t)i * 32 * H_ + ko);         \
        br[i] = *(const float4*)(Bptr + (size_t)i * 32 * H_ + ko);         \
    } }

#define STORET() {                                                         \
    _Pragma("unroll")                                                      \
    for (int i = 0; i < 4; i++) {                                          \
        uint4 ua = make_uint4(f2tf(ar[i].x), f2tf(ar[i].y),                \
                              f2tf(ar[i].z), f2tf(ar[i].w));               \
        *(uint4*)&As[rowB + i * 32][kq * 4] = ua;                          \
        uint4 ub = make_uint4(f2tf(br[i].x), f2tf(br[i].y),                \
                              f2tf(br[i].z), f2tf(br[i].w));               \
        *(uint4*)&Bs[rowB + i * 32][kq * 4] = ub;                          \
    } }

#define COMPUTE() {                                                        \
    _Pragma("unroll")                                                      \
    for (int ks = 0; ks < 4; ks++) {                                       \
        const int k0 = ks * 8;                                             \
        uint32_t af[4][4];                                                 \
        uint32_t bf[4][2];                                                 \
        _Pragma("unroll")                                                  \
        for (int mi = 0; mi < 4; mi++) {                                   \
            int r0 = warpM * 64 + mi * 16 + g;                             \
            af[mi][0] = As[r0][k0 + t];                                    \
            af[mi][1] = As[r0 + 8][k0 + t];                                \
            af[mi][2] = As[r0][k0 + t + 4];                                \
            af[mi][3] = As[r0 + 8][k0 + t + 4];                            \
        }                                                                  \
        _Pragma("unroll")                                                  \
        for (int ni = 0; ni < 4; ni++) {                                   \
            int n0 = warpN * 32 + ni * 8 + g;                              \
            bf[ni][0] = Bs[n0][k0 + t];                                    \
            bf[ni][1] = Bs[n0][k0 + t + 4];                                \
        }                                                                  \
        _Pragma("unroll")                                                  \
        for (int mi = 0; mi < 4; mi++)                                     \
            _Pragma("unroll")                                              \
            for (int ni = 0; ni < 4; ni++)                                 \
                mma_tf32(acc[mi][ni], af[mi], bf[ni]);                     \
    } }

    LOADT(0);
    STORET();
    __syncthreads();

    #pragma unroll 1
    for (int kt = 0; kt < 32; kt++) {
        if (kt < 31) LOADT(kt + 1);
        COMPUTE();
        __syncthreads();
        if (kt < 31) {
            STORET();
            __syncthreads();
        }
    }

    // Epilogue: energy = tanh(acc + dec_proj), partial = sum_col energy * v
    float rs[8];
    #pragma unroll
    for (int i = 0; i < 8; i++) rs[i] = 0.f;

    #pragma unroll
    for (int mi = 0; mi < 4; mi++) {
        #pragma unroll
        for (int ni = 0; ni < 4; ni++) {
            int c0 = warpN * 32 + ni * 8 + 2 * t;
            float d0 = dp_sh[c0],     d1 = dp_sh[c0 + 1];
            float w0 = v_sh[c0],      w1 = v_sh[c0 + 1];
            rs[2 * mi]     += tanhf(acc[mi][ni][0] + d0) * w0
                            + tanhf(acc[mi][ni][1] + d1) * w1;
            rs[2 * mi + 1] += tanhf(acc[mi][ni][2] + d0) * w0
                            + tanhf(acc[mi][ni][3] + d1) * w1;
        }
    }
    // reduce across the 4 t-lanes sharing each row
    #pragma unroll
    for (int i = 0; i < 8; i++) {
        rs[i] += __shfl_xor_sync(0xffffffffu, rs[i], 1);
        rs[i] += __shfl_xor_sync(0xffffffffu, rs[i], 2);
    }
    if (t == 0) {
        #pragma unroll
        for (int mi = 0; mi < 4; mi++) {
            part_sh[warpN][warpM * 64 + mi * 16 + g]     = rs[2 * mi];
            part_sh[warpN][warpM * 64 + mi * 16 + g + 8] = rs[2 * mi + 1];
        }
    }
    __syncthreads();
    if (tid < 128) {
        float sres = part_sh[0][tid] + part_sh[1][tid]
                   + part_sh[2][tid] + part_sh[3][tid];
        g_part[(size_t)blockIdx.x * M_ + mBase + tid] = sres;
    }
#undef LOADT
#undef STORET
#undef COMPUTE
}

// ---------------------------------------------------------------------------
// Kernel 3: per-batch softmax over S (with mask), writes attn weights.
// Mask dtype resolved at runtime via g_mask_mode (sniffed from data).
// ---------------------------------------------------------------------------
__global__ void softmax_kernel(const void* __restrict__ mask,
                               float* __restrict__ attn) {
    const int b   = blockIdx.x;
    const int tid = threadIdx.x;  // 256
    __shared__ float red[8];
    const int mode = g_mask_mode;

    float vals[8];
    float lmax = -1e30f;
    #pragma unroll
    for (int i = 0; i < 8; i++) {
        size_t f = (size_t)b * S_ + tid + i * 256;
        float sc = 0.f;
        #pragma unroll
        for (int x = 0; x < NTILES; x++) sc += g_part[(size_t)x * M_ + f];
        bool alive;
        if (mode == 0)      alive = ((const unsigned char*)mask)[f] != 0;
        else if (mode == 1) alive = ((const int*)mask)[f] != 0;
        else                alive = ((const float*)mask)[f] != 0.0f;
        if (!alive) sc = -1e9f;
        vals[i] = sc;
        lmax = fmaxf(lmax, sc);
    }
    float m = lmax;
    #pragma unroll
    for (int off = 16; off; off >>= 1)
        m = fmaxf(m, __shfl_xor_sync(0xffffffffu, m, off));
    if ((tid & 31) == 0) red[tid >> 5] = m;
    __syncthreads();
    float bm = red[0];
    #pragma unroll
    for (int i = 1; i < 8; i++) bm = fmaxf(bm, red[i]);

    float lsum = 0.f;
    #pragma unroll
    for (int i = 0; i < 8; i++) {
        vals[i] = expf(vals[i] - bm);
        lsum += vals[i];
    }
    #pragma unroll
    for (int off = 16; off; off >>= 1)
        lsum += __shfl_xor_sync(0xffffffffu, lsum, off);
    __syncthreads();                 // red[] reuse
    if ((tid & 31) == 0) red[tid >> 5] = lsum;
    __syncthreads();
    float tot = 0.f;
    #pragma unroll
    for (int i = 0; i < 8; i++) tot += red[i];
    float inv = 1.f / tot;

    #pragma unroll
    for (int i = 0; i < 8; i++)
        attn[(size_t)b * S_ + tid + i * 256] = vals[i] * inv;
}

// ---------------------------------------------------------------------------
// Kernel 4: context[b][h] = sum_s attn[b,s] * enc[b,s,h]   (HBM-bound)
// grid (64, 8): block covers one b, 128 h-columns; 2-way s-split in-block.
// ---------------------------------------------------------------------------
__global__ void context_kernel(const float* __restrict__ enc,
                               const float* __restrict__ attn,
                               float* __restrict__ ctx) {
    const int b  = blockIdx.x;
    const int h  = blockIdx.y * 128 + (threadIdx.x & 127);
    const int sp = threadIdx.x >> 7;  // 0/1
    const float* e = enc  + (size_t)b * S_ * H_ + h;
    const float* w = attn + (size_t)b * S_;
    float acc = 0.f;
    #pragma unroll 8
    for (int s = sp; s < S_; s += 2)
        acc = fmaf(w[s], e[(size_t)s * H_], acc);
    __shared__ float sh[256];
    sh[threadIdx.x] = acc;
    __syncthreads();
    if (threadIdx.x < 128)
        ctx[(size_t)b * H_ + h] = sh[threadIdx.x] + sh[threadIdx.x + 128];
}

// ---------------------------------------------------------------------------
extern "C" void kernel_launch(void* const* d_in, const int* in_sizes, int n_in,
                              void* d_out, int out_size) {
    (void)in_sizes; (void)n_in; (void)out_size;
    const float* dec  = (const float*)d_in[0];          // [B,H]
    const float* enc  = (const float*)d_in[1];          // [B,S,H]
    const void*  mask = (const void*)d_in[2];           // [B,S] bool (dtype sniffed)
    const float* Wenc = (const float*)d_in[3];          // [H,H]
    const float* Wdec = (const float*)d_in[4];          // [H,H]
    const float* v    = (const float*)d_in[5];          // [H]
    float* out  = (float*)d_out;        // [B*H context | B*S attn]
    float* attn = out + (size_t)B_ * H_;

    sniff_mask_kernel<<<1, 1>>>((const unsigned int*)mask);
    dec_proj_kernel<<<2048, 256>>>(dec, Wdec);
    dim3 g2(NTILES, M_ / 128);          // x = N-tile fastest -> L2 reuse of A
    fused_score_kernel<<<g2, 256>>>(enc, Wenc, v);
    softmax_kernel<<<B_, 256>>>(mask, attn);
    context_kernel<<<dim3(B_, H_ / 128), 256>>>(enc, attn, out);
}

// round 4
// speedup vs baseline: 1.0482x; 1.0482x over previous
#include <cuda_runtime.h>
#include <cuda_fp16.h>
#include <cstdint>
#include <math.h>

#define B_ 64
#define S_ 2048
#define H_ 1024
#define M_ (B_*S_)
#define NTILES 8          // H_/128 N-blocks
#define KT 32             // k floats per tile
#define K_ITERS (H_/KT)   // 32
#define RS 80             // smem row stride bytes (padded, conflict-free)
#define STAGE (128*RS)    // 10240 B per operand stage

__device__ float g_dp[B_ * H_];
__device__ float g_part[NTILES * M_];
__device__ int   g_mask_mode;

__device__ __forceinline__ uint32_t smem_u32(const void* p) {
    uint32_t a;
    asm("{ .reg .u64 t; cvta.to.shared.u64 t, %1; cvt.u32.u64 %0, t; }" : "=r"(a) : "l"(p));
    return a;
}
__device__ __forceinline__ uint32_t pack_h2(float lo, float hi) {
    __half2 h = __floats2half2_rn(lo, hi);
    return *(uint32_t*)&h;
}
__device__ __forceinline__ void ldsm_x4(uint32_t r[4], uint32_t addr) {
    asm volatile("ldmatrix.sync.aligned.m8n8.x4.shared.b16 {%0,%1,%2,%3}, [%4];"
                 : "=r"(r[0]), "=r"(r[1]), "=r"(r[2]), "=r"(r[3]) : "r"(addr));
}
__device__ __forceinline__ void mma_f16(float c[4], const uint32_t a[4],
                                        uint32_t b0, uint32_t b1) {
    asm volatile(
        "mma.sync.aligned.m16n8k16.row.col.f32.f16.f16.f32 "
        "{%0,%1,%2,%3}, {%4,%5,%6,%7}, {%8,%9}, {%0,%1,%2,%3};"
        : "+f"(c[0]), "+f"(c[1]), "+f"(c[2]), "+f"(c[3])
        : "r"(a[0]), "r"(a[1]), "r"(a[2]), "r"(a[3]), "r"(b0), "r"(b1));
}
__device__ __forceinline__ float fast_tanh(float x) {
    float y; asm("tanh.approx.f32 %0, %1;" : "=f"(y) : "f"(x)); return y;
}

// ---------------------------------------------------------------------------
__global__ void sniff_mask_kernel(const unsigned int* __restrict__ m) {
    unsigned w = m[0];
    int mode;
    if (w == 0x01010101u)      mode = 0;  // uint8/bool
    else if (w == 0x3F800000u) mode = 2;  // float32
    else                       mode = 1;  // int32
    g_mask_mode = mode;
}

// ---------------------------------------------------------------------------
__global__ void dec_proj_kernel(const float* __restrict__ dec,
                                const float* __restrict__ Wdec) {
    int wid  = (blockIdx.x * blockDim.x + threadIdx.x) >> 5;
    int lane = threadIdx.x & 31;
    int o  = wid >> 4;
    int b0 = (wid & 15) * 4;
    const float* wr = Wdec + (size_t)o * H_;
    const float* d0 = dec + (size_t)(b0 + 0) * H_;
    const float* d1 = dec + (size_t)(b0 + 1) * H_;
    const float* d2 = dec + (size_t)(b0 + 2) * H_;
    const float* d3 = dec + (size_t)(b0 + 3) * H_;
    float a0 = 0.f, a1 = 0.f, a2 = 0.f, a3 = 0.f;
    #pragma unroll 4
    for (int h = lane; h < H_; h += 32) {
        float w = wr[h];
        a0 = fmaf(w, d0[h], a0);
        a1 = fmaf(w, d1[h], a1);
        a2 = fmaf(w, d2[h], a2);
        a3 = fmaf(w, d3[h], a3);
    }
    #pragma unroll
    for (int off = 16; off; off >>= 1) {
        a0 += __shfl_down_sync(0xffffffffu, a0, off);
        a1 += __shfl_down_sync(0xffffffffu, a1, off);
        a2 += __shfl_down_sync(0xffffffffu, a2, off);
        a3 += __shfl_down_sync(0xffffffffu, a3, off);
    }
    if (lane == 0) {
        g_dp[(size_t)(b0 + 0) * H_ + o] = a0;
        g_dp[(size_t)(b0 + 1) * H_ + o] = a1;
        g_dp[(size_t)(b0 + 2) * H_ + o] = a2;
        g_dp[(size_t)(b0 + 3) * H_ + o] = a3;
    }
}

// ---------------------------------------------------------------------------
// Fused fp16 MMA GEMM (enc @ W_enc^T) + tanh(.+dec_proj).v partial reduction.
// Block 128(M)x128(N), k-tile 32, double-buffered smem, ldmatrix fragments.
// 8 warps: 2(M) x 4(N); warp tile 64x32.
// ---------------------------------------------------------------------------
__global__ void __launch_bounds__(256, 1)
fused_score_kernel(const float* __restrict__ enc,
                   const float* __restrict__ Wenc,
                   const float* __restrict__ v) {
    __shared__ __align__(16) char smA[2][STAGE];
    __shared__ __align__(16) char smB[2][STAGE];
    __shared__ float dp_sh[128];
    __shared__ float v_sh[128];
    __shared__ float part_sh[4][128];

    const int tid   = threadIdx.x;
    const int lane  = tid & 31;
    const int warp  = tid >> 5;
    const int warpM = warp & 1;
    const int warpN = warp >> 1;
    const int g = lane >> 2;
    const int t = lane & 3;

    const int nBase = blockIdx.x * 128;
    const int mBase = blockIdx.y * 128;
    const int b     = mBase >> 11;

    if (tid < 128) {
        dp_sh[tid] = g_dp[(size_t)b * H_ + nBase + tid];
        v_sh[tid]  = v[nBase + tid];
    }

    const uint32_t smA0 = smem_u32(&smA[0][0]);
    const uint32_t smB0 = smem_u32(&smB[0][0]);

    float acc[4][4][4];
    #pragma unroll
    for (int mi = 0; mi < 4; mi++)
        #pragma unroll
        for (int ni = 0; ni < 4; ni++)
            #pragma unroll
            for (int c = 0; c < 4; c++) acc[mi][ni][c] = 0.f;

    // global staging: thread owns half a row (16 floats) of A and of B per ktile
    const int rowG  = tid >> 1;          // 0..127
    const int halfG = tid & 1;           // 0/1 -> k offset 16 floats
    const float* Ag = enc  + (size_t)(mBase + rowG) * H_ + halfG * 16;
    const float* Bg = Wenc + (size_t)(nBase + rowG) * H_ + halfG * 16;
    const uint32_t stBase = rowG * RS + halfG * 32;   // 16 floats -> 32 bytes f16

    float4 ar[4], br[4];

#define LOADG(KTI) {                                                        \
    const size_t ko = (size_t)(KTI) * KT;                                   \
    _Pragma("unroll")                                                       \
    for (int i = 0; i < 4; i++) {                                           \
        ar[i] = *(const float4*)(Ag + ko + i * 4);                          \
        br[i] = *(const float4*)(Bg + ko + i * 4);                          \
    } }

#define STORES(BUF) {                                                      \
    uint32_t ha[8], hb[8];                                                  \
    _Pragma("unroll")                                                       \
    for (int i = 0; i < 4; i++) {                                           \
        ha[2*i]   = pack_h2(ar[i].x, ar[i].y);                              \
        ha[2*i+1] = pack_h2(ar[i].z, ar[i].w);                              \
        hb[2*i]   = pack_h2(br[i].x, br[i].y);                              \
        hb[2*i+1] = pack_h2(br[i].z, br[i].w);                              \
    }                                                                       \
    uint32_t da = smA0 + (BUF) * STAGE + stBase;                            \
    uint32_t db = smB0 + (BUF) * STAGE + stBase;                            \
    asm volatile("st.shared.v4.b32 [%0], {%1,%2,%3,%4};" ::                 \
        "r"(da), "r"(ha[0]), "r"(ha[1]), "r"(ha[2]), "r"(ha[3]));           \
    asm volatile("st.shared.v4.b32 [%0], {%1,%2,%3,%4};" ::                 \
        "r"(da + 16), "r"(ha[4]), "r"(ha[5]), "r"(ha[6]), "r"(ha[7]));      \
    asm volatile("st.shared.v4.b32 [%0], {%1,%2,%3,%4};" ::                 \
        "r"(db), "r"(hb[0]), "r"(hb[1]), "r"(hb[2]), "r"(hb[3]));           \
    asm volatile("st.shared.v4.b32 [%0], {%1,%2,%3,%4};" ::                 \
        "r"(db + 16), "r"(hb[4]), "r"(hb[5]), "r"(hb[6]), "r"(hb[7]));      \
    }

    // ldmatrix per-lane address components
    const int aRow = warpM * 64 + (lane & 7) + ((lane >> 3) & 1) * 8;
    const int aCol = ((lane >> 4) & 1) * 16;
    const int bRow = warpN * 32 + (lane >> 4) * 8 + (lane & 7);
    const int bCol = ((lane >> 3) & 1) * 16;

#define COMPUTE(BUF) {                                                     \
    const uint32_t Ab = smA0 + (BUF) * STAGE;                               \
    const uint32_t Bb = smB0 + (BUF) * STAGE;                               \
    _Pragma("unroll")                                                       \
    for (int ks = 0; ks < 2; ks++) {                                        \
        uint32_t af[4][4], bf[2][4];                                        \
        _Pragma("unroll")                                                   \
        for (int mi = 0; mi < 4; mi++)                                      \
            ldsm_x4(af[mi], Ab + (aRow + mi * 16) * RS + ks * 32 + aCol);   \
        _Pragma("unroll")                                                   \
        for (int nj = 0; nj < 2; nj++)                                      \
            ldsm_x4(bf[nj], Bb + (bRow + nj * 16) * RS + ks * 32 + bCol);   \
        _Pragma("unroll")                                                   \
        for (int mi = 0; mi < 4; mi++) {                                    \
            _Pragma("unroll")                                               \
            for (int nj = 0; nj < 2; nj++) {                                \
                mma_f16(acc[mi][2*nj],   af[mi], bf[nj][0], bf[nj][1]);     \
                mma_f16(acc[mi][2*nj+1], af[mi], bf[nj][2], bf[nj][3]);     \
            }                                                               \
        }                                                                   \
    } }

    LOADG(0);
    STORES(0);
    __syncthreads();

    #pragma unroll 1
    for (int kt = 0; kt < K_ITERS; kt++) {
        if (kt + 1 < K_ITERS) LOADG(kt + 1);
        COMPUTE(kt & 1);
        if (kt + 1 < K_ITERS) {
            STORES((kt + 1) & 1);
            __syncthreads();
        }
    }
#undef LOADG
#undef STORES
#undef COMPUTE

    // Epilogue: energy = tanh(acc + dec_proj), partial = sum_col energy * v
    float rs[8];
    #pragma unroll
    for (int i = 0; i < 8; i++) rs[i] = 0.f;

    #pragma unroll
    for (int mi = 0; mi < 4; mi++) {
        #pragma unroll
        for (int ni = 0; ni < 4; ni++) {
            int c0 = warpN * 32 + ni * 8 + 2 * t;
            float d0 = dp_sh[c0],     d1 = dp_sh[c0 + 1];
            float w0 = v_sh[c0],      w1 = v_sh[c0 + 1];
            rs[2 * mi]     += fast_tanh(acc[mi][ni][0] + d0) * w0
                            + fast_tanh(acc[mi][ni][1] + d1) * w1;
            rs[2 * mi + 1] += fast_tanh(acc[mi][ni][2] + d0) * w0
                            + fast_tanh(acc[mi][ni][3] + d1) * w1;
        }
    }
    #pragma unroll
    for (int i = 0; i < 8; i++) {
        rs[i] += __shfl_xor_sync(0xffffffffu, rs[i], 1);
        rs[i] += __shfl_xor_sync(0xffffffffu, rs[i], 2);
    }
    if (t == 0) {
        #pragma unroll
        for (int mi = 0; mi < 4; mi++) {
            part_sh[warpN][warpM * 64 + mi * 16 + g]     = rs[2 * mi];
            part_sh[warpN][warpM * 64 + mi * 16 + g + 8] = rs[2 * mi + 1];
        }
    }
    __syncthreads();
    if (tid < 128) {
        float sres = part_sh[0][tid] + part_sh[1][tid]
                   + part_sh[2][tid] + part_sh[3][tid];
        g_part[(size_t)blockIdx.x * M_ + mBase + tid] = sres;
    }
}

// ---------------------------------------------------------------------------
__global__ void softmax_kernel(const void* __restrict__ mask,
                               float* __restrict__ attn) {
    const int b   = blockIdx.x;
    const int tid = threadIdx.x;  // 256
    __shared__ float red[8];
    const int mode = g_mask_mode;

    float vals[8];
    float lmax = -1e30f;
    #pragma unroll
    for (int i = 0; i < 8; i++) {
        size_t f = (size_t)b * S_ + tid + i * 256;
        float sc = 0.f;
        #pragma unroll
        for (int x = 0; x < NTILES; x++) sc += g_part[(size_t)x * M_ + f];
        bool alive;
        if (mode == 0)      alive = ((const unsigned char*)mask)[f] != 0;
        else if (mode == 1) alive = ((const int*)mask)[f] != 0;
        else                alive = ((const float*)mask)[f] != 0.0f;
        if (!alive) sc = -1e9f;
        vals[i] = sc;
        lmax = fmaxf(lmax, sc);
    }
    float m = lmax;
    #pragma unroll
    for (int off = 16; off; off >>= 1)
        m = fmaxf(m, __shfl_xor_sync(0xffffffffu, m, off));
    if ((tid & 31) == 0) red[tid >> 5] = m;
    __syncthreads();
    float bm = red[0];
    #pragma unroll
    for (int i = 1; i < 8; i++) bm = fmaxf(bm, red[i]);

    float lsum = 0.f;
    #pragma unroll
    for (int i = 0; i < 8; i++) {
        vals[i] = expf(vals[i] - bm);
        lsum += vals[i];
    }
    #pragma unroll
    for (int off = 16; off; off >>= 1)
        lsum += __shfl_xor_sync(0xffffffffu, lsum, off);
    __syncthreads();
    if ((tid & 31) == 0) red[tid >> 5] = lsum;
    __syncthreads();
    float tot = 0.f;
    #pragma unroll
    for (int i = 0; i < 8; i++) tot += red[i];
    float inv = 1.f / tot;

    #pragma unroll
    for (int i = 0; i < 8; i++)
        attn[(size_t)b * S_ + tid + i * 256] = vals[i] * inv;
}

// ---------------------------------------------------------------------------
__global__ void context_kernel(const float* __restrict__ enc,
                               const float* __restrict__ attn,
                               float* __restrict__ ctx) {
    const int b  = blockIdx.x;
    const int h  = blockIdx.y * 128 + (threadIdx.x & 127);
    const int sp = threadIdx.x >> 7;
    const float* e = enc  + (size_t)b * S_ * H_ + h;
    const float* w = attn + (size_t)b * S_;
    float acc = 0.f;
    #pragma unroll 8
    for (int s = sp; s < S_; s += 2)
        acc = fmaf(w[s], e[(size_t)s * H_], acc);
    __shared__ float sh[256];
    sh[threadIdx.x] = acc;
    __syncthreads();
    if (threadIdx.x < 128)
        ctx[(size_t)b * H_ + h] = sh[threadIdx.x] + sh[threadIdx.x + 128];
}

// ---------------------------------------------------------------------------
extern "C" void kernel_launch(void* const* d_in, const int* in_sizes, int n_in,
                              void* d_out, int out_size) {
    (void)in_sizes; (void)n_in; (void)out_size;
    const float* dec  = (const float*)d_in[0];
    const float* enc  = (const float*)d_in[1];
    const void*  mask = (const void*)d_in[2];
    const float* Wenc = (const float*)d_in[3];
    const float* Wdec = (const float*)d_in[4];
    const float* v    = (const float*)d_in[5];
    float* out  = (float*)d_out;
    float* attn = out + (size_t)B_ * H_;

    sniff_mask_kernel<<<1, 1>>>((const unsigned int*)mask);
    dec_proj_kernel<<<2048, 256>>>(dec, Wdec);
    dim3 g2(NTILES, M_ / 128);      // (8, 1024), x fastest -> A reuse in L2
    fused_score_kernel<<<g2, 256>>>(enc, Wenc, v);
    softmax_kernel<<<B_, 256>>>(mask, attn);
    context_kernel<<<dim3(B_, H_ / 128), 256>>>(enc, attn, out);
}